// round 6
// baseline (speedup 1.0000x reference)
#include <cuda_runtime.h>
#include <cuda_bf16.h>
#include <math.h>
#include <stdint.h>

// Problem constants
#define Bsz 2
#define Sq  2048
#define Dm  512
#define Vv  32000
#define Ll  3
#define ROWS (Bsz*Sq)      // 4096
#define BD   (ROWS*Dm)     // 2097152
#define SSZ  (Bsz*Sq*Sq)   // 8388608
#define INV_SCALE 0.125f

// ---------------- fp32 scratch ----------------
__device__ float g_x[BD];
__device__ float g_out[BD];
__device__ float g_h[BD];
__device__ float g_h2[BD];
__device__ float g_t[BD];
__device__ float g_a[BD];
__device__ float g_s[SSZ];

// ---------------- bf16 split scratch ----------------
__device__ __nv_bfloat16 sx_h[BD],  sx_l[BD];
__device__ __nv_bfloat16 so_h[BD],  so_l[BD];
__device__ __nv_bfloat16 sh_h[BD],  sh_l[BD];
__device__ __nv_bfloat16 sh2_h[BD], sh2_l[BD];
__device__ __nv_bfloat16 sq_h[BD],  sq_l[BD];
__device__ __nv_bfloat16 sk_h[BD],  sk_l[BD];
__device__ __nv_bfloat16 sv_h[BD],  sv_l[BD];
__device__ __nv_bfloat16 svt_h[BD], svt_l[BD];
__device__ __nv_bfloat16 sp_h[SSZ], sp_l[SSZ];
__device__ __nv_bfloat16 sw_h[(long)Vv*Dm], sw_l[(long)Vv*Dm];

// ================= helpers =================
__device__ __forceinline__ uint32_t smem_u32(const void* p) {
    uint32_t a;
    asm("{ .reg .u64 t; cvta.to.shared.u64 t, %1; cvt.u32.u64 %0, t; }" : "=r"(a) : "l"(p));
    return a;
}
#define CP_ASYNC(dst, src) asm volatile("cp.async.cg.shared.global [%0], [%1], 16;" :: "r"(dst), "l"(src) : "memory")
#define CP_COMMIT()        asm volatile("cp.async.commit_group;" ::: "memory")
#define CP_WAIT(n)         asm volatile("cp.async.wait_group %0;" :: "n"(n) : "memory")

__device__ __forceinline__ void ldmx4(uint32_t& r0, uint32_t& r1, uint32_t& r2, uint32_t& r3, uint32_t a) {
    asm volatile("ldmatrix.sync.aligned.m8n8.x4.shared.b16 {%0,%1,%2,%3}, [%4];"
                 : "=r"(r0), "=r"(r1), "=r"(r2), "=r"(r3) : "r"(a));
}
__device__ __forceinline__ void mma_bf16(float* d, const uint32_t* a, const uint32_t* b) {
    asm volatile(
        "mma.sync.aligned.m16n8k16.row.col.f32.bf16.bf16.f32 "
        "{%0,%1,%2,%3}, {%4,%5,%6,%7}, {%8,%9}, {%0,%1,%2,%3};"
        : "+f"(d[0]), "+f"(d[1]), "+f"(d[2]), "+f"(d[3])
        : "r"(a[0]), "r"(a[1]), "r"(a[2]), "r"(a[3]), "r"(b[0]), "r"(b[1]));
}
__device__ __forceinline__ void split1(float x, __nv_bfloat16& h, __nv_bfloat16& l) {
    h = __float2bfloat16(x);
    l = __float2bfloat16(x - __bfloat162float(h));
}
// SW128 swizzle for a 128-row x 64-bf16 (128B/row) tile. c = 16B chunk 0..7.
__device__ __forceinline__ uint32_t swz(int r, int c) {
    return (uint32_t)(r * 128 + ((c ^ (r & 7)) * 16));
}

// ================= GEMM: C = alpha * A @ B^T (+bias | split out) ============
// A: [M,K] bf16 hi/lo; B: [N,K] bf16 hi/lo. bf16x3: Ah*Bh + Ah*Bl + Al*Bh.
// BM=BN=128, BK=64, 512 threads (16 warps: 4 M x 4 N, warp tile 32x32),
// 3-stage cp.async pipeline, 192KB dynamic smem.
#define TILEB 16384
#define STAGEB (4*TILEB)
#define GEMM_SMEM (3*STAGEB)

template<bool HAS_BIAS, bool SPLIT>
__global__ void __launch_bounds__(512, 1) gemm3(
    const __nv_bfloat16* __restrict__ Ah, const __nv_bfloat16* __restrict__ Al,
    const __nv_bfloat16* __restrict__ Bh, const __nv_bfloat16* __restrict__ Bl,
    const float* __restrict__ bias,
    float* __restrict__ C, __nv_bfloat16* __restrict__ Ch, __nv_bfloat16* __restrict__ Cl,
    int M, int N, int K, float alpha, long sA, long sB, long sC)
{
    extern __shared__ char smem[];
    const uint32_t sb = smem_u32(smem);
    const int tid = threadIdx.x, lane = tid & 31, wid = tid >> 5;
    const int wm = wid >> 2, wn = wid & 3;          // 4 M-warps x 4 N-warps
    const int bz = blockIdx.z;
    Ah += (long)bz * sA;  Al += (long)bz * sA;
    Bh += (long)bz * sB;  Bl += (long)bz * sB;

    const long rA0 = (long)blockIdx.y * 128;
    const long rB0 = (long)blockIdx.x * 128;

    // loader: 1024 16B-chunks per 16KB subtile; 512 threads x 2 chunks each
    uint32_t soff[2];
    long goff[2];
    #pragma unroll
    for (int i = 0; i < 2; i++) {
        const int q = tid + i * 512;
        const int r = q >> 3, c = q & 7;
        soff[i] = swz(r, c);
        goff[i] = (long)r * K + c * 8;
    }
    const __nv_bfloat16* gAh = Ah + rA0 * K;
    const __nv_bfloat16* gAl = Al + rA0 * K;
    const __nv_bfloat16* gBh = Bh + rB0 * K;
    const __nv_bfloat16* gBl = Bl + rB0 * K;

    float acc[2][4][4];
    #pragma unroll
    for (int i = 0; i < 2; i++)
        #pragma unroll
        for (int j = 0; j < 4; j++)
            #pragma unroll
            for (int q = 0; q < 4; q++) acc[i][j][q] = 0.f;

    const int nk = K >> 6;

    auto load_tile = [&](int st, int k0) {
        const uint32_t s = sb + st * STAGEB;
        #pragma unroll
        for (int i = 0; i < 2; i++) {
            CP_ASYNC(s + 0*TILEB + soff[i], gAh + goff[i] + k0);
            CP_ASYNC(s + 1*TILEB + soff[i], gAl + goff[i] + k0);
            CP_ASYNC(s + 2*TILEB + soff[i], gBh + goff[i] + k0);
            CP_ASYNC(s + 3*TILEB + soff[i], gBl + goff[i] + k0);
        }
    };

    load_tile(0, 0);  CP_COMMIT();
    load_tile(1, 64); CP_COMMIT();

    int st = 0;
    for (int kt = 0; kt < nk; kt++) {
        if (kt + 1 < nk) { CP_WAIT(1); } else { CP_WAIT(0); }
        __syncthreads();
        if (kt + 2 < nk) {
            int st2 = st + 2; if (st2 >= 3) st2 -= 3;
            load_tile(st2, (kt + 2) << 6);
            CP_COMMIT();
        }

        const uint32_t s0  = sb + st * STAGEB;
        const uint32_t sAH = s0, sAL = s0 + TILEB, sBH = s0 + 2*TILEB, sBL = s0 + 3*TILEB;
        const int arow = wm * 32 + (lane & 15);
        const int brow = wn * 32 + ((lane >> 4) << 3) + (lane & 7);

        #pragma unroll
        for (int ks = 0; ks < 4; ks++) {
            const int achk = ks * 2 + (lane >> 4);
            const int bchk = ks * 2 + ((lane >> 3) & 1);
            uint32_t ah[2][4], al[2][4];
            #pragma unroll
            for (int mi = 0; mi < 2; mi++) {
                const uint32_t off = swz(arow + mi * 16, achk);
                ldmx4(ah[mi][0], ah[mi][1], ah[mi][2], ah[mi][3], sAH + off);
                ldmx4(al[mi][0], al[mi][1], al[mi][2], al[mi][3], sAL + off);
            }
            uint32_t bh[4][2], bl[4][2];
            #pragma unroll
            for (int nj = 0; nj < 2; nj++) {
                const uint32_t off = swz(brow + nj * 16, bchk);
                uint32_t t0, t1, t2, t3;
                ldmx4(t0, t1, t2, t3, sBH + off);
                bh[2*nj][0] = t0; bh[2*nj][1] = t1; bh[2*nj+1][0] = t2; bh[2*nj+1][1] = t3;
                ldmx4(t0, t1, t2, t3, sBL + off);
                bl[2*nj][0] = t0; bl[2*nj][1] = t1; bl[2*nj+1][0] = t2; bl[2*nj+1][1] = t3;
            }
            #pragma unroll
            for (int mi = 0; mi < 2; mi++)
                #pragma unroll
                for (int ni = 0; ni < 4; ni++) {
                    mma_bf16(acc[mi][ni], ah[mi], bh[ni]);
                    mma_bf16(acc[mi][ni], ah[mi], bl[ni]);
                    mma_bf16(acc[mi][ni], al[mi], bh[ni]);
                }
        }
        st++; if (st >= 3) st = 0;
    }

    // epilogue
    const long rbase = rA0 + wm * 32 + (lane >> 2);
    const int  cbase = blockIdx.x * 128 + wn * 32 + (lane & 3) * 2;
    #pragma unroll
    for (int mi = 0; mi < 2; mi++) {
        #pragma unroll
        for (int ni = 0; ni < 4; ni++) {
            const int cc = cbase + ni * 8;
            float v00 = alpha * acc[mi][ni][0], v01 = alpha * acc[mi][ni][1];
            float v10 = alpha * acc[mi][ni][2], v11 = alpha * acc[mi][ni][3];
            if (HAS_BIAS) {
                v00 += bias[cc]; v01 += bias[cc + 1];
                v10 += bias[cc]; v11 += bias[cc + 1];
            }
            const long r0 = (long)bz * sC + (rbase + mi * 16) * N;
            const long r1 = r0 + 8 * N;
            if (SPLIT) {
                __nv_bfloat16 h0, l0, h1, l1;
                split1(v00, h0, l0); split1(v01, h1, l1);
                *(__nv_bfloat162*)(Ch + r0 + cc) = {h0, h1};
                *(__nv_bfloat162*)(Cl + r0 + cc) = {l0, l1};
                split1(v10, h0, l0); split1(v11, h1, l1);
                *(__nv_bfloat162*)(Ch + r1 + cc) = {h0, h1};
                *(__nv_bfloat162*)(Cl + r1 + cc) = {l0, l1};
            } else {
                *(float2*)(C + r0 + cc) = {v00, v01};
                *(float2*)(C + r1 + cc) = {v10, v11};
            }
        }
    }
}

// ================= conversion kernels =================
__global__ void convsplit(const float* __restrict__ in,
                          __nv_bfloat16* __restrict__ oh, __nv_bfloat16* __restrict__ ol, long n)
{
    long i = ((long)blockIdx.x * blockDim.x + threadIdx.x) * 4;
    if (i >= n) return;
    float4 v = *(const float4*)(in + i);
    __nv_bfloat16 h0, h1, h2, h3, l0, l1, l2, l3;
    split1(v.x, h0, l0); split1(v.y, h1, l1); split1(v.z, h2, l2); split1(v.w, h3, l3);
    __nv_bfloat162 hh0 = {h0, h1}, hh1 = {h2, h3}, ll0 = {l0, l1}, ll1 = {l2, l3};
    *(uint2*)(oh + i) = make_uint2(*(uint32_t*)&hh0, *(uint32_t*)&hh1);
    *(uint2*)(ol + i) = make_uint2(*(uint32_t*)&ll0, *(uint32_t*)&ll1);
}

// transpose + split: fp32 [R,C] -> bf16 hi/lo [C,R]
__global__ void __launch_bounds__(256) tconvsplit(
    const float* __restrict__ in, __nv_bfloat16* __restrict__ oh, __nv_bfloat16* __restrict__ ol,
    int R, int C)
{
    __shared__ float t[32][33];
    const int c0 = blockIdx.x * 32, r0 = blockIdx.y * 32;
    const int tx = threadIdx.x, ty = threadIdx.y;
    #pragma unroll
    for (int j = 0; j < 32; j += 8)
        t[ty + j][tx] = in[(long)(r0 + ty + j) * C + c0 + tx];
    __syncthreads();
    #pragma unroll
    for (int j = 0; j < 32; j += 8) {
        float v = t[tx][ty + j];
        __nv_bfloat16 h, l;
        split1(v, h, l);
        long o = (long)(c0 + ty + j) * R + r0 + tx;
        oh[o] = h; ol[o] = l;
    }
}

// bf16 pair transpose: [R,C] -> [C,R], batched
__global__ void __launch_bounds__(256) tbf16(
    const __nv_bfloat16* __restrict__ ih, const __nv_bfloat16* __restrict__ il,
    __nv_bfloat16* __restrict__ oh, __nv_bfloat16* __restrict__ ol,
    int R, int C, long sIO)
{
    __shared__ __nv_bfloat16 th[32][33], tl[32][33];
    ih += (long)blockIdx.z * sIO;  il += (long)blockIdx.z * sIO;
    oh += (long)blockIdx.z * sIO;  ol += (long)blockIdx.z * sIO;
    const int c0 = blockIdx.x * 32, r0 = blockIdx.y * 32;
    const int tx = threadIdx.x, ty = threadIdx.y;
    #pragma unroll
    for (int j = 0; j < 32; j += 8) {
        long idx = (long)(r0 + ty + j) * C + c0 + tx;
        th[ty + j][tx] = ih[idx];
        tl[ty + j][tx] = il[idx];
    }
    __syncthreads();
    #pragma unroll
    for (int j = 0; j < 32; j += 8) {
        long o = (long)(c0 + ty + j) * R + r0 + tx;
        oh[o] = th[tx][ty + j];
        ol[o] = tl[tx][ty + j];
    }
}

// ================= online softmax =================
__device__ __forceinline__ void sm_merge(float& m, float& s, float m2, float s2) {
    float M = fmaxf(m, m2);
    s = s * __expf(m - M) + s2 * __expf(m2 - M);
    m = M;
}
__device__ __forceinline__ void block_softmax_stats(float& m, float& s) {
    __shared__ float shm[32], shs[32];
    const int lane = threadIdx.x & 31, w = threadIdx.x >> 5;
    #pragma unroll
    for (int o = 16; o; o >>= 1)
        sm_merge(m, s, __shfl_xor_sync(0xffffffffu, m, o), __shfl_xor_sync(0xffffffffu, s, o));
    if (lane == 0) { shm[w] = m; shs[w] = s; }
    __syncthreads();
    const int nw = blockDim.x >> 5;
    if (w == 0) {
        float mm = (lane < nw) ? shm[lane] : -1e30f;
        float ss = (lane < nw) ? shs[lane] : 0.f;
        #pragma unroll
        for (int o = 16; o; o >>= 1)
            sm_merge(mm, ss, __shfl_xor_sync(0xffffffffu, mm, o), __shfl_xor_sync(0xffffffffu, ss, o));
        if (lane == 0) { shm[0] = mm; shs[0] = ss; }
    }
    __syncthreads();
    m = shm[0]; s = shs[0];
    __syncthreads();
}

__global__ void softmax_kernel(float* __restrict__ data, int N) {
    float* row = data + (size_t)blockIdx.x * N;
    float m = -1e30f, s = 0.f;
    for (int i = threadIdx.x; i < N; i += blockDim.x) {
        float v = row[i];
        float mo = m;
        m = fmaxf(m, v);
        s = s * __expf(mo - m) + __expf(v - m);
    }
    block_softmax_stats(m, s);
    const float inv = 1.f / s;
    for (int i = threadIdx.x; i < N; i += blockDim.x)
        row[i] = __expf(row[i] - m) * inv;
}

__global__ void softmax_split_kernel(const float* __restrict__ in,
                                     __nv_bfloat16* __restrict__ oh, __nv_bfloat16* __restrict__ ol, int N)
{
    const float* row = in + (size_t)blockIdx.x * N;
    float m = -1e30f, s = 0.f;
    for (int i = threadIdx.x; i < N; i += blockDim.x) {
        float v = row[i];
        float mo = m;
        m = fmaxf(m, v);
        s = s * __expf(mo - m) + __expf(v - m);
    }
    block_softmax_stats(m, s);
    const float inv = 1.f / s;
    const size_t base = (size_t)blockIdx.x * N;
    for (int i = threadIdx.x; i < N; i += blockDim.x) {
        float p = __expf(row[i] - m) * inv;
        __nv_bfloat16 h, l;
        split1(p, h, l);
        oh[base + i] = h; ol[base + i] = l;
    }
}

// ========== fused (silu?)+residual+LayerNorm, fp32 out + split out ==========
template<bool SILU, bool AFFINE>
__global__ void __launch_bounds__(128) addln_kernel(
    const float* __restrict__ a, const float* __restrict__ res,
    const float* __restrict__ g, const float* __restrict__ bta,
    float* __restrict__ out, __nv_bfloat16* __restrict__ oh, __nv_bfloat16* __restrict__ ol)
{
    const int row = blockIdx.x;
    const int tid = threadIdx.x;
    float4 av = ((const float4*)(a   + (size_t)row * Dm))[tid];
    float4 rv = ((const float4*)(res + (size_t)row * Dm))[tid];
    float v[4] = {av.x, av.y, av.z, av.w};
    float r[4] = {rv.x, rv.y, rv.z, rv.w};

    float s = 0.f, s2 = 0.f;
    #pragma unroll
    for (int i = 0; i < 4; i++) {
        float t = SILU ? (v[i] / (1.f + __expf(-v[i]))) : v[i];
        t += r[i];
        v[i] = t;
        s += t; s2 += t * t;
    }
    __shared__ float ss[4], ss2[4];
    #pragma unroll
    for (int o = 16; o; o >>= 1) {
        s  += __shfl_xor_sync(0xffffffffu, s,  o);
        s2 += __shfl_xor_sync(0xffffffffu, s2, o);
    }
    const int w = tid >> 5, lane = tid & 31;
    if (lane == 0) { ss[w] = s; ss2[w] = s2; }
    __syncthreads();
    s  = ss[0]  + ss[1]  + ss[2]  + ss[3];
    s2 = ss2[0] + ss2[1] + ss2[2] + ss2[3];

    const float mean = s * (1.f / Dm);
    const float var  = s2 * (1.f / Dm) - mean * mean;
    const float inv  = rsqrtf(var + 1e-5f);

    float ov[4];
    __nv_bfloat16 hh[4], ll[4];
    #pragma unroll
    for (int i = 0; i < 4; i++) {
        float yv = (v[i] - mean) * inv;
        if (AFFINE) {
            const int c = tid * 4 + i;
            yv = yv * g[c] + bta[c];
        }
        ov[i] = yv;
        split1(yv, hh[i], ll[i]);
    }
    float4 o4 = {ov[0], ov[1], ov[2], ov[3]};
    ((float4*)(out + (size_t)row * Dm))[tid] = o4;
    __nv_bfloat162 h0 = {hh[0], hh[1]}, h1 = {hh[2], hh[3]};
    __nv_bfloat162 l0 = {ll[0], ll[1]}, l1 = {ll[2], ll[3]};
    ((uint2*)(oh + (size_t)row * Dm))[tid] = make_uint2(*(uint32_t*)&h0, *(uint32_t*)&h1);
    ((uint2*)(ol + (size_t)row * Dm))[tid] = make_uint2(*(uint32_t*)&l0, *(uint32_t*)&l1);
}

// ================= host-side orchestration =================
struct Ptrs {
    float *gx, *gout, *gh, *gh2, *gt, *ga, *gs;
    __nv_bfloat16 *xh, *xl, *oh, *ol, *hh, *hl, *h2h, *h2l;
    __nv_bfloat16 *qh, *ql, *kh, *kl, *vh, *vl, *vth, *vtl, *ph, *pl, *wh, *wl;
};

static void G(const __nv_bfloat16* Ah, const __nv_bfloat16* Al,
              const __nv_bfloat16* Bh, const __nv_bfloat16* Bl,
              const float* bias, float* C, __nv_bfloat16* Ch, __nv_bfloat16* Cl,
              int M, int N, int K, float alpha, int batch,
              long sA, long sB, long sC)
{
    dim3 grid(N / 128, M / 128, batch), block(512);
    if (Ch)        gemm3<false, true ><<<grid, block, GEMM_SMEM>>>(Ah, Al, Bh, Bl, bias, C, Ch, Cl, M, N, K, alpha, sA, sB, sC);
    else if (bias) gemm3<true , false><<<grid, block, GEMM_SMEM>>>(Ah, Al, Bh, Bl, bias, C, Ch, Cl, M, N, K, alpha, sA, sB, sC);
    else           gemm3<false, false><<<grid, block, GEMM_SMEM>>>(Ah, Al, Bh, Bl, bias, C, Ch, Cl, M, N, K, alpha, sA, sB, sC);
}

static void tconv(const float* in, __nv_bfloat16* oh, __nv_bfloat16* ol, int R, int C) {
    dim3 grid(C / 32, R / 32), block(32, 8);
    tconvsplit<<<grid, block>>>(in, oh, ol, R, C);
}

static void run_attn(const Ptrs& P,
                     const __nv_bfloat16* qh_in, const __nv_bfloat16* ql_in,
                     const __nv_bfloat16* ch_in, const __nv_bfloat16* cl_in,
                     const float* wq, const float* wk, const float* wv,
                     const float* resid, float* outp,
                     __nv_bfloat16* out_h, __nv_bfloat16* out_l)
{
    tconv(wq, P.wh, P.wl, Dm, Dm);
    G(qh_in, ql_in, P.wh, P.wl, nullptr, nullptr, P.qh, P.ql, ROWS, Dm, Dm, 1.f, 1, 0, 0, 0);
    tconv(wk, P.wh, P.wl, Dm, Dm);
    G(ch_in, cl_in, P.wh, P.wl, nullptr, nullptr, P.kh, P.kl, ROWS, Dm, Dm, 1.f, 1, 0, 0, 0);
    tconv(wv, P.wh, P.wl, Dm, Dm);
    G(ch_in, cl_in, P.wh, P.wl, nullptr, nullptr, P.vh, P.vl, ROWS, Dm, Dm, 1.f, 1, 0, 0, 0);

    G(P.qh, P.ql, P.kh, P.kl, nullptr, P.gs, nullptr, nullptr, Sq, Sq, Dm, INV_SCALE, Bsz,
      (long)Sq * Dm, (long)Sq * Dm, (long)Sq * Sq);
    softmax_split_kernel<<<ROWS, 256>>>(P.gs, P.ph, P.pl, Sq);
    {
        dim3 grid(Dm / 32, Sq / 32, Bsz), block(32, 8);
        tbf16<<<grid, block>>>(P.vh, P.vl, P.vth, P.vtl, Sq, Dm, (long)Sq * Dm);
    }
    G(P.ph, P.pl, P.vth, P.vtl, nullptr, P.ga, nullptr, nullptr, Sq, Dm, Sq, 1.f, Bsz,
      (long)Sq * Sq, (long)Sq * Dm, (long)Sq * Dm);
    addln_kernel<false, false><<<ROWS, 128>>>(P.ga, resid, nullptr, nullptr, outp, out_h, out_l);
}

extern "C" void kernel_launch(void* const* d_in, const int* in_sizes, int n_in,
                              void* d_out, int out_size)
{
    const float* x       = (const float*)d_in[0];
    const float* y       = (const float*)d_in[1];
    const float* enc_wq  = (const float*)d_in[2];
    const float* enc_wk  = (const float*)d_in[3];
    const float* enc_wv  = (const float*)d_in[4];
    const float* enc_fw  = (const float*)d_in[5];
    const float* enc_fb  = (const float*)d_in[6];
    const float* enc_g   = (const float*)d_in[7];
    const float* enc_b   = (const float*)d_in[8];
    const float* dec_swq = (const float*)d_in[9];
    const float* dec_swk = (const float*)d_in[10];
    const float* dec_swv = (const float*)d_in[11];
    const float* dec_cwq = (const float*)d_in[12];
    const float* dec_cwk = (const float*)d_in[13];
    const float* dec_cwv = (const float*)d_in[14];
    const float* dec_fw  = (const float*)d_in[15];
    const float* dec_fb  = (const float*)d_in[16];
    const float* dec_g   = (const float*)d_in[17];
    const float* dec_b   = (const float*)d_in[18];
    const float* fc_w    = (const float*)d_in[19];

    cudaFuncSetAttribute(gemm3<false, false>, cudaFuncAttributeMaxDynamicSharedMemorySize, GEMM_SMEM);
    cudaFuncSetAttribute(gemm3<false, true >, cudaFuncAttributeMaxDynamicSharedMemorySize, GEMM_SMEM);
    cudaFuncSetAttribute(gemm3<true , false>, cudaFuncAttributeMaxDynamicSharedMemorySize, GEMM_SMEM);

    Ptrs P;
    cudaGetSymbolAddress((void**)&P.gx,   g_x);
    cudaGetSymbolAddress((void**)&P.gout, g_out);
    cudaGetSymbolAddress((void**)&P.gh,   g_h);
    cudaGetSymbolAddress((void**)&P.gh2,  g_h2);
    cudaGetSymbolAddress((void**)&P.gt,   g_t);
    cudaGetSymbolAddress((void**)&P.ga,   g_a);
    cudaGetSymbolAddress((void**)&P.gs,   g_s);
    cudaGetSymbolAddress((void**)&P.xh,  sx_h);   cudaGetSymbolAddress((void**)&P.xl,  sx_l);
    cudaGetSymbolAddress((void**)&P.oh,  so_h);   cudaGetSymbolAddress((void**)&P.ol,  so_l);
    cudaGetSymbolAddress((void**)&P.hh,  sh_h);   cudaGetSymbolAddress((void**)&P.hl,  sh_l);
    cudaGetSymbolAddress((void**)&P.h2h, sh2_h);  cudaGetSymbolAddress((void**)&P.h2l, sh2_l);
    cudaGetSymbolAddress((void**)&P.qh,  sq_h);   cudaGetSymbolAddress((void**)&P.ql,  sq_l);
    cudaGetSymbolAddress((void**)&P.kh,  sk_h);   cudaGetSymbolAddress((void**)&P.kl,  sk_l);
    cudaGetSymbolAddress((void**)&P.vh,  sv_h);   cudaGetSymbolAddress((void**)&P.vl,  sv_l);
    cudaGetSymbolAddress((void**)&P.vth, svt_h);  cudaGetSymbolAddress((void**)&P.vtl, svt_l);
    cudaGetSymbolAddress((void**)&P.ph,  sp_h);   cudaGetSymbolAddress((void**)&P.pl,  sp_l);
    cudaGetSymbolAddress((void**)&P.wh,  sw_h);   cudaGetSymbolAddress((void**)&P.wl,  sw_l);

    cudaMemcpyAsync(P.gx,   x, (size_t)BD * sizeof(float), cudaMemcpyDeviceToDevice);
    cudaMemcpyAsync(P.gout, y, (size_t)BD * sizeof(float), cudaMemcpyDeviceToDevice);
    convsplit<<<(BD / 4 + 255) / 256, 256>>>(x, P.xh, P.xl, BD);
    convsplit<<<(BD / 4 + 255) / 256, 256>>>(y, P.oh, P.ol, BD);

    const long DD = (long)Dm * Dm;

    // -------- encoder stacks --------
    for (int i = 0; i < Ll; i++) {
        run_attn(P, P.xh, P.xl, P.xh, P.xl,
                 enc_wq + i * DD, enc_wk + i * DD, enc_wv + i * DD,
                 P.gx, P.gh, P.hh, P.hl);
        tconv(enc_fw + i * DD, P.wh, P.wl, Dm, Dm);
        G(P.hh, P.hl, P.wh, P.wl, enc_fb + i * Dm, P.gt, nullptr, nullptr, ROWS, Dm, Dm, 1.f, 1, 0, 0, 0);
        addln_kernel<true, true><<<ROWS, 128>>>(P.gt, P.gh, enc_g + i * Dm, enc_b + i * Dm, P.gx, P.xh, P.xl);
    }

    // -------- decoder stacks --------
    for (int i = 0; i < Ll; i++) {
        run_attn(P, P.xh, P.xl, P.xh, P.xl,
                 dec_swq + i * DD, dec_swk + i * DD, dec_swv + i * DD,
                 P.gx, P.gh, P.hh, P.hl);
        run_attn(P, P.hh, P.hl, P.oh, P.ol,
                 dec_cwq + i * DD, dec_cwk + i * DD, dec_cwv + i * DD,
                 P.gh, P.gh2, P.h2h, P.h2l);
        tconv(dec_fw + i * DD, P.wh, P.wl, Dm, Dm);
        G(P.h2h, P.h2l, P.wh, P.wl, dec_fb + i * Dm, P.gt, nullptr, nullptr, ROWS, Dm, Dm, 1.f, 1, 0, 0, 0);
        addln_kernel<true, true><<<ROWS, 128>>>(P.gt, P.gh2, dec_g + i * Dm, dec_b + i * Dm, P.gout, P.oh, P.ol);
    }

    // -------- vocab head + softmax --------
    tconv(fc_w, P.wh, P.wl, Dm, Vv);
    float* logits = (float*)d_out;
    G(P.oh, P.ol, P.wh, P.wl, nullptr, logits, nullptr, nullptr, ROWS, Vv, Dm, 1.f, 1, 0, 0, 0);
    softmax_kernel<<<ROWS, 512>>>(logits, Vv);
}

// round 7
// speedup vs baseline: 1.3148x; 1.3148x over previous
#include <cuda_runtime.h>
#include <cuda_fp16.h>
#include <math.h>
#include <stdint.h>

// Problem constants
#define Bsz 2
#define Sq  2048
#define Dm  512
#define Vv  32000
#define Ll  3
#define ROWS (Bsz*Sq)      // 4096
#define BD   (ROWS*Dm)     // 2097152
#define SSZ  (Bsz*Sq*Sq)   // 8388608
#define INV_SCALE 0.125f

// ---------------- fp32 scratch ----------------
__device__ float g_x[BD];
__device__ float g_out[BD];
__device__ float g_h[BD];
__device__ float g_h2[BD];
__device__ float g_t[BD];
__device__ float g_a[BD];
__device__ float g_s[SSZ];

// ---------------- fp16 scratch ----------------
// A-side (single fp16): activations
__device__ __half sx[BD];      // encoder state
__device__ __half so[BD];      // decoder state
__device__ __half sh[BD];      // attn-out
__device__ __half sh2[BD];     // attn2-out
__device__ __half sq[BD];      // Q
__device__ __half sp[SSZ];     // softmax probs
// B-side (split fp16 hi/lo)
__device__ __half skh[BD],  skl[BD];    // K
__device__ __half svh[BD],  svl[BD];    // V
__device__ __half svth[BD], svtl[BD];   // V^T
__device__ __half swh[(long)Vv*Dm], swl[(long)Vv*Dm]; // weights^T

// ================= helpers =================
__device__ __forceinline__ uint32_t smem_u32(const void* p) {
    uint32_t a;
    asm("{ .reg .u64 t; cvta.to.shared.u64 t, %1; cvt.u32.u64 %0, t; }" : "=r"(a) : "l"(p));
    return a;
}
#define CP_ASYNC(dst, src) asm volatile("cp.async.cg.shared.global [%0], [%1], 16;" :: "r"(dst), "l"(src) : "memory")
#define CP_COMMIT()        asm volatile("cp.async.commit_group;" ::: "memory")
#define CP_WAIT(n)         asm volatile("cp.async.wait_group %0;" :: "n"(n) : "memory")

__device__ __forceinline__ void ldmx4(uint32_t& r0, uint32_t& r1, uint32_t& r2, uint32_t& r3, uint32_t a) {
    asm volatile("ldmatrix.sync.aligned.m8n8.x4.shared.b16 {%0,%1,%2,%3}, [%4];"
                 : "=r"(r0), "=r"(r1), "=r"(r2), "=r"(r3) : "r"(a));
}
__device__ __forceinline__ void mma_f16(float* d, const uint32_t* a, const uint32_t* b) {
    asm volatile(
        "mma.sync.aligned.m16n8k16.row.col.f32.f16.f16.f32 "
        "{%0,%1,%2,%3}, {%4,%5,%6,%7}, {%8,%9}, {%0,%1,%2,%3};"
        : "+f"(d[0]), "+f"(d[1]), "+f"(d[2]), "+f"(d[3])
        : "r"(a[0]), "r"(a[1]), "r"(a[2]), "r"(a[3]), "r"(b[0]), "r"(b[1]));
}
__device__ __forceinline__ void split1h(float x, __half& h, __half& l) {
    h = __float2half(x);
    l = __float2half(x - __half2float(h));
}
// SW128 swizzle for a 128-row x 64-half (128B/row) tile. c = 16B chunk 0..7.
__device__ __forceinline__ uint32_t swz(int r, int c) {
    return (uint32_t)(r * 128 + ((c ^ (r & 7)) * 16));
}

// ================= GEMM: C = alpha * A @ B^T (+bias) fp16x2 =================
// A: [M,K] fp16 single; B: [N,K] fp16 hi/lo. C = Ah*Bh + Ah*Bl (fp32 accum).
// BM=BN=128, BK=64, 256 threads (8 warps: 4 M x 2 N, warp tile 32x64),
// 3-stage cp.async pipeline, 144KB dynamic smem.
// OUTM: 0 = fp32, 1 = single fp16, 2 = split fp16 pair
#define TILEB 16384
#define STAGEB (3*TILEB)
#define GEMM_SMEM (3*STAGEB)

template<int OUTM, bool HAS_BIAS>
__global__ void __launch_bounds__(256, 1) gemm2(
    const __half* __restrict__ A,
    const __half* __restrict__ Bh, const __half* __restrict__ Bl,
    const float* __restrict__ bias,
    float* __restrict__ C, __half* __restrict__ Ch, __half* __restrict__ Cl,
    int M, int N, int K, float alpha, long sA, long sB, long sC)
{
    extern __shared__ char smem[];
    const uint32_t sb = smem_u32(smem);
    const int tid = threadIdx.x, lane = tid & 31, wid = tid >> 5;
    const int wm = wid >> 1, wn = wid & 1;          // 4 M-warps x 2 N-warps
    const int bz = blockIdx.z;
    A  += (long)bz * sA;
    Bh += (long)bz * sB;  Bl += (long)bz * sB;

    const long rA0 = (long)blockIdx.y * 128;
    const long rB0 = (long)blockIdx.x * 128;

    // loader: 1024 16B-chunks per 16KB subtile; 256 threads x 4 positions
    uint32_t soff[4];
    long goff[4];
    #pragma unroll
    for (int i = 0; i < 4; i++) {
        const int q = tid + i * 256;
        const int r = q >> 3, c = q & 7;
        soff[i] = swz(r, c);
        goff[i] = (long)r * K + c * 8;
    }
    const __half* gA  = A  + rA0 * K;
    const __half* gBh = Bh + rB0 * K;
    const __half* gBl = Bl + rB0 * K;

    float acc[2][8][4];
    #pragma unroll
    for (int i = 0; i < 2; i++)
        #pragma unroll
        for (int j = 0; j < 8; j++)
            #pragma unroll
            for (int q = 0; q < 4; q++) acc[i][j][q] = 0.f;

    const int nk = K >> 6;

    auto load_tile = [&](int st, int k0) {
        const uint32_t s = sb + st * STAGEB;
        #pragma unroll
        for (int i = 0; i < 4; i++) {
            CP_ASYNC(s + 0*TILEB + soff[i], gA  + goff[i] + k0);
            CP_ASYNC(s + 1*TILEB + soff[i], gBh + goff[i] + k0);
            CP_ASYNC(s + 2*TILEB + soff[i], gBl + goff[i] + k0);
        }
    };

    load_tile(0, 0);  CP_COMMIT();
    load_tile(1, 64); CP_COMMIT();

    int st = 0;
    for (int kt = 0; kt < nk; kt++) {
        if (kt + 1 < nk) { CP_WAIT(1); } else { CP_WAIT(0); }
        __syncthreads();
        if (kt + 2 < nk) {
            int st2 = st + 2; if (st2 >= 3) st2 -= 3;
            load_tile(st2, (kt + 2) << 6);
            CP_COMMIT();
        }

        const uint32_t s0  = sb + st * STAGEB;
        const uint32_t sA0 = s0, sBH = s0 + TILEB, sBL = s0 + 2*TILEB;
        const int arow = wm * 32 + (lane & 15);
        const int brow = wn * 64 + ((lane >> 4) << 3) + (lane & 7);

        #pragma unroll
        for (int ks = 0; ks < 4; ks++) {
            const int achk = ks * 2 + (lane >> 4);
            const int bchk = ks * 2 + ((lane >> 3) & 1);
            uint32_t ah[2][4];
            #pragma unroll
            for (int mi = 0; mi < 2; mi++) {
                const uint32_t off = swz(arow + mi * 16, achk);
                ldmx4(ah[mi][0], ah[mi][1], ah[mi][2], ah[mi][3], sA0 + off);
            }
            uint32_t bh[8][2], bl[8][2];
            #pragma unroll
            for (int nj = 0; nj < 4; nj++) {
                const uint32_t off = swz(brow + nj * 16, bchk);
                uint32_t t0, t1, t2, t3;
                ldmx4(t0, t1, t2, t3, sBH + off);
                bh[2*nj][0] = t0; bh[2*nj][1] = t1; bh[2*nj+1][0] = t2; bh[2*nj+1][1] = t3;
                ldmx4(t0, t1, t2, t3, sBL + off);
                bl[2*nj][0] = t0; bl[2*nj][1] = t1; bl[2*nj+1][0] = t2; bl[2*nj+1][1] = t3;
            }
            #pragma unroll
            for (int mi = 0; mi < 2; mi++)
                #pragma unroll
                for (int ni = 0; ni < 8; ni++) {
                    mma_f16(acc[mi][ni], ah[mi], bh[ni]);
                    mma_f16(acc[mi][ni], ah[mi], bl[ni]);
                }
        }
        st++; if (st >= 3) st = 0;
    }

    // epilogue
    const long rbase = rA0 + wm * 32 + (lane >> 2);
    const int  cbase = blockIdx.x * 128 + wn * 64 + (lane & 3) * 2;
    #pragma unroll
    for (int mi = 0; mi < 2; mi++) {
        #pragma unroll
        for (int ni = 0; ni < 8; ni++) {
            const int cc = cbase + ni * 8;
            float v00 = alpha * acc[mi][ni][0], v01 = alpha * acc[mi][ni][1];
            float v10 = alpha * acc[mi][ni][2], v11 = alpha * acc[mi][ni][3];
            if (HAS_BIAS) {
                v00 += bias[cc]; v01 += bias[cc + 1];
                v10 += bias[cc]; v11 += bias[cc + 1];
            }
            const long r0 = (long)bz * sC + (rbase + mi * 16) * N;
            const long r1 = r0 + 8 * N;
            if (OUTM == 0) {
                *(float2*)(C + r0 + cc) = {v00, v01};
                *(float2*)(C + r1 + cc) = {v10, v11};
            } else if (OUTM == 1) {
                *(__half2*)(Ch + r0 + cc) = __halves2half2(__float2half(v00), __float2half(v01));
                *(__half2*)(Ch + r1 + cc) = __halves2half2(__float2half(v10), __float2half(v11));
            } else {
                __half h0, l0, h1, l1;
                split1h(v00, h0, l0); split1h(v01, h1, l1);
                *(__half2*)(Ch + r0 + cc) = __halves2half2(h0, h1);
                *(__half2*)(Cl + r0 + cc) = __halves2half2(l0, l1);
                split1h(v10, h0, l0); split1h(v11, h1, l1);
                *(__half2*)(Ch + r1 + cc) = __halves2half2(h0, h1);
                *(__half2*)(Cl + r1 + cc) = __halves2half2(l0, l1);
            }
        }
    }
}

// ================= conversion kernels =================
// fp32 -> single fp16
__global__ void convh(const float* __restrict__ in, __half* __restrict__ o, long n)
{
    long i = ((long)blockIdx.x * blockDim.x + threadIdx.x) * 4;
    if (i >= n) return;
    float4 v = *(const float4*)(in + i);
    __half2 a = __halves2half2(__float2half(v.x), __float2half(v.y));
    __half2 b = __halves2half2(__float2half(v.z), __float2half(v.w));
    *(uint2*)(o + i) = make_uint2(*(uint32_t*)&a, *(uint32_t*)&b);
}

// transpose + split: fp32 [R,C] -> fp16 hi/lo [C,R]
__global__ void __launch_bounds__(256) tconvsplit(
    const float* __restrict__ in, __half* __restrict__ oh, __half* __restrict__ ol,
    int R, int C)
{
    __shared__ float t[32][33];
    const int c0 = blockIdx.x * 32, r0 = blockIdx.y * 32;
    const int tx = threadIdx.x, ty = threadIdx.y;
    #pragma unroll
    for (int j = 0; j < 32; j += 8)
        t[ty + j][tx] = in[(long)(r0 + ty + j) * C + c0 + tx];
    __syncthreads();
    #pragma unroll
    for (int j = 0; j < 32; j += 8) {
        float v = t[tx][ty + j];
        __half h, l;
        split1h(v, h, l);
        long o = (long)(c0 + ty + j) * R + r0 + tx;
        oh[o] = h; ol[o] = l;
    }
}

// fp16 pair transpose: [R,C] -> [C,R], batched
__global__ void __launch_bounds__(256) thpair(
    const __half* __restrict__ ih, const __half* __restrict__ il,
    __half* __restrict__ oh, __half* __restrict__ ol,
    int R, int C, long sIO)
{
    __shared__ __half th[32][33], tl[32][33];
    ih += (long)blockIdx.z * sIO;  il += (long)blockIdx.z * sIO;
    oh += (long)blockIdx.z * sIO;  ol += (long)blockIdx.z * sIO;
    const int c0 = blockIdx.x * 32, r0 = blockIdx.y * 32;
    const int tx = threadIdx.x, ty = threadIdx.y;
    #pragma unroll
    for (int j = 0; j < 32; j += 8) {
        long idx = (long)(r0 + ty + j) * C + c0 + tx;
        th[ty + j][tx] = ih[idx];
        tl[ty + j][tx] = il[idx];
    }
    __syncthreads();
    #pragma unroll
    for (int j = 0; j < 32; j += 8) {
        long o = (long)(c0 + ty + j) * R + r0 + tx;
        oh[o] = th[tx][ty + j];
        ol[o] = tl[tx][ty + j];
    }
}

// ================= online softmax =================
__device__ __forceinline__ void sm_merge(float& m, float& s, float m2, float s2) {
    float M = fmaxf(m, m2);
    s = s * __expf(m - M) + s2 * __expf(m2 - M);
    m = M;
}
__device__ __forceinline__ void block_softmax_stats(float& m, float& s) {
    __shared__ float shm[32], shs[32];
    const int lane = threadIdx.x & 31, w = threadIdx.x >> 5;
    #pragma unroll
    for (int o = 16; o; o >>= 1)
        sm_merge(m, s, __shfl_xor_sync(0xffffffffu, m, o), __shfl_xor_sync(0xffffffffu, s, o));
    if (lane == 0) { shm[w] = m; shs[w] = s; }
    __syncthreads();
    const int nw = blockDim.x >> 5;
    if (w == 0) {
        float mm = (lane < nw) ? shm[lane] : -1e30f;
        float ss = (lane < nw) ? shs[lane] : 0.f;
        #pragma unroll
        for (int o = 16; o; o >>= 1)
            sm_merge(mm, ss, __shfl_xor_sync(0xffffffffu, mm, o), __shfl_xor_sync(0xffffffffu, ss, o));
        if (lane == 0) { shm[0] = mm; shs[0] = ss; }
    }
    __syncthreads();
    m = shm[0]; s = shs[0];
    __syncthreads();
}

__global__ void softmax_kernel(float* __restrict__ data, int N) {
    float* row = data + (size_t)blockIdx.x * N;
    float m = -1e30f, s = 0.f;
    for (int i = threadIdx.x; i < N; i += blockDim.x) {
        float v = row[i];
        float mo = m;
        m = fmaxf(m, v);
        s = s * __expf(mo - m) + __expf(v - m);
    }
    block_softmax_stats(m, s);
    const float inv = 1.f / s;
    for (int i = threadIdx.x; i < N; i += blockDim.x)
        row[i] = __expf(row[i] - m) * inv;
}

// softmax writing single fp16 probs
__global__ void softmax_h_kernel(const float* __restrict__ in, __half* __restrict__ o, int N)
{
    const float* row = in + (size_t)blockIdx.x * N;
    float m = -1e30f, s = 0.f;
    for (int i = threadIdx.x; i < N; i += blockDim.x) {
        float v = row[i];
        float mo = m;
        m = fmaxf(m, v);
        s = s * __expf(mo - m) + __expf(v - m);
    }
    block_softmax_stats(m, s);
    const float inv = 1.f / s;
    const size_t base = (size_t)blockIdx.x * N;
    for (int i = threadIdx.x; i < N; i += blockDim.x)
        o[base + i] = __float2half(__expf(row[i] - m) * inv);
}

// ====== fused (silu?)+residual+LayerNorm, fp32 out + single fp16 out ======
template<bool SILU, bool AFFINE>
__global__ void __launch_bounds__(128) addln_kernel(
    const float* __restrict__ a, const float* __restrict__ res,
    const float* __restrict__ g, const float* __restrict__ bta,
    float* __restrict__ out, __half* __restrict__ oh)
{
    const int row = blockIdx.x;
    const int tid = threadIdx.x;
    float4 av = ((const float4*)(a   + (size_t)row * Dm))[tid];
    float4 rv = ((const float4*)(res + (size_t)row * Dm))[tid];
    float v[4] = {av.x, av.y, av.z, av.w};
    float r[4] = {rv.x, rv.y, rv.z, rv.w};

    float s = 0.f, s2 = 0.f;
    #pragma unroll
    for (int i = 0; i < 4; i++) {
        float t = SILU ? (v[i] / (1.f + __expf(-v[i]))) : v[i];
        t += r[i];
        v[i] = t;
        s += t; s2 += t * t;
    }
    __shared__ float ss[4], ss2[4];
    #pragma unroll
    for (int o = 16; o; o >>= 1) {
        s  += __shfl_xor_sync(0xffffffffu, s,  o);
        s2 += __shfl_xor_sync(0xffffffffu, s2, o);
    }
    const int w = tid >> 5, lane = tid & 31;
    if (lane == 0) { ss[w] = s; ss2[w] = s2; }
    __syncthreads();
    s  = ss[0]  + ss[1]  + ss[2]  + ss[3];
    s2 = ss2[0] + ss2[1] + ss2[2] + ss2[3];

    const float mean = s * (1.f / Dm);
    const float var  = s2 * (1.f / Dm) - mean * mean;
    const float inv  = rsqrtf(var + 1e-5f);

    float ov[4];
    #pragma unroll
    for (int i = 0; i < 4; i++) {
        float yv = (v[i] - mean) * inv;
        if (AFFINE) {
            const int c = tid * 4 + i;
            yv = yv * g[c] + bta[c];
        }
        ov[i] = yv;
    }
    float4 o4 = {ov[0], ov[1], ov[2], ov[3]};
    ((float4*)(out + (size_t)row * Dm))[tid] = o4;
    __half2 h0 = __halves2half2(__float2half(ov[0]), __float2half(ov[1]));
    __half2 h1 = __halves2half2(__float2half(ov[2]), __float2half(ov[3]));
    ((uint2*)(oh + (size_t)row * Dm))[tid] = make_uint2(*(uint32_t*)&h0, *(uint32_t*)&h1);
}

// ================= host-side orchestration =================
struct Ptrs {
    float *gx, *gout, *gh, *gh2, *gt, *ga, *gs;
    __half *x1, *o1, *h1, *h21, *q1, *p1;
    __half *kh, *kl, *vh, *vl, *vth, *vtl, *wh, *wl;
};

static void G(const __half* A, const __half* Bh, const __half* Bl,
              const float* bias, float* C, __half* Ch, __half* Cl, int outm,
              int M, int N, int K, float alpha, int batch,
              long sA, long sB, long sC)
{
    dim3 grid(N / 128, M / 128, batch), block(256);
    if (outm == 2)      gemm2<2, false><<<grid, block, GEMM_SMEM>>>(A, Bh, Bl, bias, C, Ch, Cl, M, N, K, alpha, sA, sB, sC);
    else if (outm == 1) gemm2<1, false><<<grid, block, GEMM_SMEM>>>(A, Bh, Bl, bias, C, Ch, Cl, M, N, K, alpha, sA, sB, sC);
    else if (bias)      gemm2<0, true ><<<grid, block, GEMM_SMEM>>>(A, Bh, Bl, bias, C, Ch, Cl, M, N, K, alpha, sA, sB, sC);
    else                gemm2<0, false><<<grid, block, GEMM_SMEM>>>(A, Bh, Bl, bias, C, Ch, Cl, M, N, K, alpha, sA, sB, sC);
}

static void tconv(const float* in, __half* oh, __half* ol, int R, int C) {
    dim3 grid(C / 32, R / 32), block(32, 8);
    tconvsplit<<<grid, block>>>(in, oh, ol, R, C);
}

// attention: out = LN( softmax((q@Wq)(ctx@Wk)^T/8) @ (ctx@Wv) + resid )
static void run_attn(const Ptrs& P,
                     const __half* q_in, const __half* c_in,
                     const float* wq, const float* wk, const float* wv,
                     const float* resid, float* outp, __half* out_h)
{
    tconv(wq, P.wh, P.wl, Dm, Dm);
    G(q_in, P.wh, P.wl, nullptr, nullptr, P.q1, nullptr, 1, ROWS, Dm, Dm, 1.f, 1, 0, 0, 0);
    tconv(wk, P.wh, P.wl, Dm, Dm);
    G(c_in, P.wh, P.wl, nullptr, nullptr, P.kh, P.kl, 2, ROWS, Dm, Dm, 1.f, 1, 0, 0, 0);
    tconv(wv, P.wh, P.wl, Dm, Dm);
    G(c_in, P.wh, P.wl, nullptr, nullptr, P.vh, P.vl, 2, ROWS, Dm, Dm, 1.f, 1, 0, 0, 0);

    // scores[b] = Q[b] @ K[b]^T / 8
    G(P.q1, P.kh, P.kl, nullptr, P.gs, nullptr, nullptr, 0, Sq, Sq, Dm, INV_SCALE, Bsz,
      (long)Sq * Dm, (long)Sq * Dm, (long)Sq * Sq);
    softmax_h_kernel<<<ROWS, 256>>>(P.gs, P.p1, Sq);
    // V^T per batch
    {
        dim3 grid(Dm / 32, Sq / 32, Bsz), block(32, 8);
        thpair<<<grid, block>>>(P.vh, P.vl, P.vth, P.vtl, Sq, Dm, (long)Sq * Dm);
    }
    // attn[b] = P[b] @ V[b]
    G(P.p1, P.vth, P.vtl, nullptr, P.ga, nullptr, nullptr, 0, Sq, Dm, Sq, 1.f, Bsz,
      (long)Sq * Sq, (long)Sq * Dm, (long)Sq * Dm);
    addln_kernel<false, false><<<ROWS, 128>>>(P.ga, resid, nullptr, nullptr, outp, out_h);
}

extern "C" void kernel_launch(void* const* d_in, const int* in_sizes, int n_in,
                              void* d_out, int out_size)
{
    const float* x       = (const float*)d_in[0];
    const float* y       = (const float*)d_in[1];
    const float* enc_wq  = (const float*)d_in[2];
    const float* enc_wk  = (const float*)d_in[3];
    const float* enc_wv  = (const float*)d_in[4];
    const float* enc_fw  = (const float*)d_in[5];
    const float* enc_fb  = (const float*)d_in[6];
    const float* enc_g   = (const float*)d_in[7];
    const float* enc_b   = (const float*)d_in[8];
    const float* dec_swq = (const float*)d_in[9];
    const float* dec_swk = (const float*)d_in[10];
    const float* dec_swv = (const float*)d_in[11];
    const float* dec_cwq = (const float*)d_in[12];
    const float* dec_cwk = (const float*)d_in[13];
    const float* dec_cwv = (const float*)d_in[14];
    const float* dec_fw  = (const float*)d_in[15];
    const float* dec_fb  = (const float*)d_in[16];
    const float* dec_g   = (const float*)d_in[17];
    const float* dec_b   = (const float*)d_in[18];
    const float* fc_w    = (const float*)d_in[19];

    cudaFuncSetAttribute(gemm2<0, false>, cudaFuncAttributeMaxDynamicSharedMemorySize, GEMM_SMEM);
    cudaFuncSetAttribute(gemm2<0, true >, cudaFuncAttributeMaxDynamicSharedMemorySize, GEMM_SMEM);
    cudaFuncSetAttribute(gemm2<1, false>, cudaFuncAttributeMaxDynamicSharedMemorySize, GEMM_SMEM);
    cudaFuncSetAttribute(gemm2<2, false>, cudaFuncAttributeMaxDynamicSharedMemorySize, GEMM_SMEM);

    Ptrs P;
    cudaGetSymbolAddress((void**)&P.gx,   g_x);
    cudaGetSymbolAddress((void**)&P.gout, g_out);
    cudaGetSymbolAddress((void**)&P.gh,   g_h);
    cudaGetSymbolAddress((void**)&P.gh2,  g_h2);
    cudaGetSymbolAddress((void**)&P.gt,   g_t);
    cudaGetSymbolAddress((void**)&P.ga,   g_a);
    cudaGetSymbolAddress((void**)&P.gs,   g_s);
    cudaGetSymbolAddress((void**)&P.x1,  sx);
    cudaGetSymbolAddress((void**)&P.o1,  so);
    cudaGetSymbolAddress((void**)&P.h1,  sh);
    cudaGetSymbolAddress((void**)&P.h21, sh2);
    cudaGetSymbolAddress((void**)&P.q1,  sq);
    cudaGetSymbolAddress((void**)&P.p1,  sp);
    cudaGetSymbolAddress((void**)&P.kh,  skh);   cudaGetSymbolAddress((void**)&P.kl,  skl);
    cudaGetSymbolAddress((void**)&P.vh,  svh);   cudaGetSymbolAddress((void**)&P.vl,  svl);
    cudaGetSymbolAddress((void**)&P.vth, svth);  cudaGetSymbolAddress((void**)&P.vtl, svtl);
    cudaGetSymbolAddress((void**)&P.wh,  swh);   cudaGetSymbolAddress((void**)&P.wl,  swl);

    cudaMemcpyAsync(P.gx,   x, (size_t)BD * sizeof(float), cudaMemcpyDeviceToDevice);
    cudaMemcpyAsync(P.gout, y, (size_t)BD * sizeof(float), cudaMemcpyDeviceToDevice);
    convh<<<(BD / 4 + 255) / 256, 256>>>(x, P.x1, BD);
    convh<<<(BD / 4 + 255) / 256, 256>>>(y, P.o1, BD);

    const long DD = (long)Dm * Dm;

    // -------- encoder stacks --------
    for (int i = 0; i < Ll; i++) {
        run_attn(P, P.x1, P.x1,
                 enc_wq + i * DD, enc_wk + i * DD, enc_wv + i * DD,
                 P.gx, P.gh, P.h1);
        tconv(enc_fw + i * DD, P.wh, P.wl, Dm, Dm);
        G(P.h1, P.wh, P.wl, enc_fb + i * Dm, P.gt, nullptr, nullptr, 0, ROWS, Dm, Dm, 1.f, 1, 0, 0, 0);
        addln_kernel<true, true><<<ROWS, 128>>>(P.gt, P.gh, enc_g + i * Dm, enc_b + i * Dm, P.gx, P.x1);
    }

    // -------- decoder stacks --------
    for (int i = 0; i < Ll; i++) {
        run_attn(P, P.x1, P.x1,
                 dec_swq + i * DD, dec_swk + i * DD, dec_swv + i * DD,
                 P.gx, P.gh, P.h1);
        run_attn(P, P.h1, P.o1,
                 dec_cwq + i * DD, dec_cwk + i * DD, dec_cwv + i * DD,
                 P.gh, P.gh2, P.h21);
        tconv(dec_fw + i * DD, P.wh, P.wl, Dm, Dm);
        G(P.h21, P.wh, P.wl, dec_fb + i * Dm, P.gt, nullptr, nullptr, 0, ROWS, Dm, Dm, 1.f, 1, 0, 0, 0);
        addln_kernel<true, true><<<ROWS, 128>>>(P.gt, P.gh2, dec_g + i * Dm, dec_b + i * Dm, P.gout, P.o1);
    }

    // -------- vocab head + softmax --------
    tconv(fc_w, P.wh, P.wl, Dm, Vv);
    float* logits = (float*)d_out;
    G(P.o1, P.wh, P.wl, nullptr, logits, nullptr, nullptr, 0, ROWS, Vv, Dm, 1.f, 1, 0, 0, 0);
    softmax_kernel<<<ROWS, 512>>>(logits, Vv);
}

// round 8
// speedup vs baseline: 1.9283x; 1.4666x over previous
#include <cuda_runtime.h>
#include <cuda_fp16.h>
#include <math.h>
#include <stdint.h>

// Problem constants
#define Bsz 2
#define Sq  2048
#define Dm  512
#define Vv  32000
#define Ll  3
#define ROWS (Bsz*Sq)      // 4096
#define BD   (ROWS*Dm)     // 2097152
#define SSZ  (Bsz*Sq*Sq)   // 8388608
#define INV_SCALE 0.125f

// ---------------- fp32 scratch ----------------
__device__ float g_x[BD];
__device__ float g_out[BD];
__device__ float g_h[BD];
__device__ float g_h2[BD];
__device__ float g_t[BD];
__device__ float g_a[BD];
__device__ float g_s[SSZ];

// ---------------- fp16 scratch ----------------
__device__ __half sx[BD];      // encoder state
__device__ __half so[BD];      // decoder state
__device__ __half sh[BD];      // attn-out
__device__ __half sh2[BD];     // attn2-out
__device__ __half sq[BD];      // Q
__device__ __half sp[SSZ];     // softmax probs
__device__ __half sk[BD];      // K
__device__ __half sv[BD];      // V
__device__ __half svt[BD];     // V^T
__device__ __half sw[(long)Vv*Dm]; // weights^T

// ================= helpers =================
__device__ __forceinline__ uint32_t smem_u32(const void* p) {
    uint32_t a;
    asm("{ .reg .u64 t; cvta.to.shared.u64 t, %1; cvt.u32.u64 %0, t; }" : "=r"(a) : "l"(p));
    return a;
}
#define CP_ASYNC(dst, src) asm volatile("cp.async.cg.shared.global [%0], [%1], 16;" :: "r"(dst), "l"(src) : "memory")
#define CP_COMMIT()        asm volatile("cp.async.commit_group;" ::: "memory")
#define CP_WAIT(n)         asm volatile("cp.async.wait_group %0;" :: "n"(n) : "memory")

__device__ __forceinline__ void ldmx4(uint32_t& r0, uint32_t& r1, uint32_t& r2, uint32_t& r3, uint32_t a) {
    asm volatile("ldmatrix.sync.aligned.m8n8.x4.shared.b16 {%0,%1,%2,%3}, [%4];"
                 : "=r"(r0), "=r"(r1), "=r"(r2), "=r"(r3) : "r"(a));
}
__device__ __forceinline__ void mma_f16(float* d, const uint32_t* a, const uint32_t* b) {
    asm volatile(
        "mma.sync.aligned.m16n8k16.row.col.f32.f16.f16.f32 "
        "{%0,%1,%2,%3}, {%4,%5,%6,%7}, {%8,%9}, {%0,%1,%2,%3};"
        : "+f"(d[0]), "+f"(d[1]), "+f"(d[2]), "+f"(d[3])
        : "r"(a[0]), "r"(a[1]), "r"(a[2]), "r"(a[3]), "r"(b[0]), "r"(b[1]));
}
// SW128 swizzle for a 128-row x 64-half (128B/row) tile. c = 16B chunk 0..7.
__device__ __forceinline__ uint32_t swz(int r, int c) {
    return (uint32_t)(r * 128 + ((c ^ (r & 7)) * 16));
}

// ================= GEMM: C = alpha * A @ B^T (+bias), fp16 x fp16 ===========
// A: [M,K] fp16; B: [N,K] fp16; fp32 accum.
// BM=BN=128, BK=64, 256 threads (8 warps: 4 M x 2 N, warp tile 32x64),
// 3-stage cp.async pipeline, 96KB dynamic smem -> 2 CTAs/SM.
// OUTM: 0 = fp32, 1 = fp16
#define TILEB 16384
#define STAGEB (2*TILEB)
#define GEMM_SMEM (3*STAGEB)

template<int OUTM, bool HAS_BIAS>
__global__ void __launch_bounds__(256, 2) gemm1(
    const __half* __restrict__ A, const __half* __restrict__ B,
    const float* __restrict__ bias,
    float* __restrict__ C, __half* __restrict__ Ch,
    int M, int N, int K, float alpha, long sA, long sB, long sC)
{
    extern __shared__ char smem[];
    const uint32_t sb = smem_u32(smem);
    const int tid = threadIdx.x, lane = tid & 31, wid = tid >> 5;
    const int wm = wid >> 1, wn = wid & 1;          // 4 M-warps x 2 N-warps
    const int bz = blockIdx.z;
    A += (long)bz * sA;
    B += (long)bz * sB;

    const long rA0 = (long)blockIdx.y * 128;
    const long rB0 = (long)blockIdx.x * 128;

    // loader: 1024 16B-chunks per 16KB subtile; 256 threads x 4 positions
    uint32_t soff[4];
    long goff[4];
    #pragma unroll
    for (int i = 0; i < 4; i++) {
        const int q = tid + i * 256;
        const int r = q >> 3, c = q & 7;
        soff[i] = swz(r, c);
        goff[i] = (long)r * K + c * 8;
    }
    const __half* gA = A + rA0 * K;
    const __half* gB = B + rB0 * K;

    float acc[2][8][4];
    #pragma unroll
    for (int i = 0; i < 2; i++)
        #pragma unroll
        for (int j = 0; j < 8; j++)
            #pragma unroll
            for (int q = 0; q < 4; q++) acc[i][j][q] = 0.f;

    const int nk = K >> 6;

    auto load_tile = [&](int st, int k0) {
        const uint32_t s = sb + st * STAGEB;
        #pragma unroll
        for (int i = 0; i < 4; i++) {
            CP_ASYNC(s + 0*TILEB + soff[i], gA + goff[i] + k0);
            CP_ASYNC(s + 1*TILEB + soff[i], gB + goff[i] + k0);
        }
    };

    load_tile(0, 0);  CP_COMMIT();
    load_tile(1, 64); CP_COMMIT();

    int st = 0;
    for (int kt = 0; kt < nk; kt++) {
        if (kt + 1 < nk) { CP_WAIT(1); } else { CP_WAIT(0); }
        __syncthreads();
        if (kt + 2 < nk) {
            int st2 = st + 2; if (st2 >= 3) st2 -= 3;
            load_tile(st2, (kt + 2) << 6);
            CP_COMMIT();
        }

        const uint32_t s0  = sb + st * STAGEB;
        const uint32_t sA0 = s0, sB0 = s0 + TILEB;
        const int arow = wm * 32 + (lane & 15);
        const int brow = wn * 64 + ((lane >> 4) << 3) + (lane & 7);

        #pragma unroll
        for (int ks = 0; ks < 4; ks++) {
            const int achk = ks * 2 + (lane >> 4);
            const int bchk = ks * 2 + ((lane >> 3) & 1);
            uint32_t ah[2][4];
            #pragma unroll
            for (int mi = 0; mi < 2; mi++) {
                const uint32_t off = swz(arow + mi * 16, achk);
                ldmx4(ah[mi][0], ah[mi][1], ah[mi][2], ah[mi][3], sA0 + off);
            }
            uint32_t bh[8][2];
            #pragma unroll
            for (int nj = 0; nj < 4; nj++) {
                const uint32_t off = swz(brow + nj * 16, bchk);
                uint32_t t0, t1, t2, t3;
                ldmx4(t0, t1, t2, t3, sB0 + off);
                bh[2*nj][0] = t0; bh[2*nj][1] = t1; bh[2*nj+1][0] = t2; bh[2*nj+1][1] = t3;
            }
            #pragma unroll
            for (int mi = 0; mi < 2; mi++)
                #pragma unroll
                for (int ni = 0; ni < 8; ni++)
                    mma_f16(acc[mi][ni], ah[mi], bh[ni]);
        }
        st++; if (st >= 3) st = 0;
    }

    // epilogue
    const long rbase = rA0 + wm * 32 + (lane >> 2);
    const int  cbase = blockIdx.x * 128 + wn * 64 + (lane & 3) * 2;
    #pragma unroll
    for (int mi = 0; mi < 2; mi++) {
        #pragma unroll
        for (int ni = 0; ni < 8; ni++) {
            const int cc = cbase + ni * 8;
            float v00 = alpha * acc[mi][ni][0], v01 = alpha * acc[mi][ni][1];
            float v10 = alpha * acc[mi][ni][2], v11 = alpha * acc[mi][ni][3];
            if (HAS_BIAS) {
                v00 += bias[cc]; v01 += bias[cc + 1];
                v10 += bias[cc]; v11 += bias[cc + 1];
            }
            const long r0 = (long)bz * sC + (rbase + mi * 16) * N;
            const long r1 = r0 + 8 * N;
            if (OUTM == 0) {
                *(float2*)(C + r0 + cc) = {v00, v01};
                *(float2*)(C + r1 + cc) = {v10, v11};
            } else {
                *(__half2*)(Ch + r0 + cc) = __halves2half2(__float2half(v00), __float2half(v01));
                *(__half2*)(Ch + r1 + cc) = __halves2half2(__float2half(v10), __float2half(v11));
            }
        }
    }
}

// ================= conversion kernels =================
__global__ void convh(const float* __restrict__ in, __half* __restrict__ o, long n)
{
    long i = ((long)blockIdx.x * blockDim.x + threadIdx.x) * 4;
    if (i >= n) return;
    float4 v = *(const float4*)(in + i);
    __half2 a = __halves2half2(__float2half(v.x), __float2half(v.y));
    __half2 b = __halves2half2(__float2half(v.z), __float2half(v.w));
    *(uint2*)(o + i) = make_uint2(*(uint32_t*)&a, *(uint32_t*)&b);
}

// transpose + convert: fp32 [R,C] -> fp16 [C,R]
__global__ void __launch_bounds__(256) tconvh(
    const float* __restrict__ in, __half* __restrict__ o, int R, int C)
{
    __shared__ float t[32][33];
    const int c0 = blockIdx.x * 32, r0 = blockIdx.y * 32;
    const int tx = threadIdx.x, ty = threadIdx.y;
    #pragma unroll
    for (int j = 0; j < 32; j += 8)
        t[ty + j][tx] = in[(long)(r0 + ty + j) * C + c0 + tx];
    __syncthreads();
    #pragma unroll
    for (int j = 0; j < 32; j += 8) {
        long ofs = (long)(c0 + ty + j) * R + r0 + tx;
        o[ofs] = __float2half(t[tx][ty + j]);
    }
}

// fp16 transpose: [R,C] -> [C,R], batched
__global__ void __launch_bounds__(256) th16(
    const __half* __restrict__ in, __half* __restrict__ o,
    int R, int C, long sIO)
{
    __shared__ __half t[32][33];
    in += (long)blockIdx.z * sIO;
    o  += (long)blockIdx.z * sIO;
    const int c0 = blockIdx.x * 32, r0 = blockIdx.y * 32;
    const int tx = threadIdx.x, ty = threadIdx.y;
    #pragma unroll
    for (int j = 0; j < 32; j += 8)
        t[ty + j][tx] = in[(long)(r0 + ty + j) * C + c0 + tx];
    __syncthreads();
    #pragma unroll
    for (int j = 0; j < 32; j += 8)
        o[(long)(c0 + ty + j) * R + r0 + tx] = t[tx][ty + j];
}

// ================= online softmax =================
__device__ __forceinline__ void sm_merge(float& m, float& s, float m2, float s2) {
    float M = fmaxf(m, m2);
    s = s * __expf(m - M) + s2 * __expf(m2 - M);
    m = M;
}
__device__ __forceinline__ void block_softmax_stats(float& m, float& s) {
    __shared__ float shm[32], shs[32];
    const int lane = threadIdx.x & 31, w = threadIdx.x >> 5;
    #pragma unroll
    for (int o = 16; o; o >>= 1)
        sm_merge(m, s, __shfl_xor_sync(0xffffffffu, m, o), __shfl_xor_sync(0xffffffffu, s, o));
    if (lane == 0) { shm[w] = m; shs[w] = s; }
    __syncthreads();
    const int nw = blockDim.x >> 5;
    if (w == 0) {
        float mm = (lane < nw) ? shm[lane] : -1e30f;
        float ss = (lane < nw) ? shs[lane] : 0.f;
        #pragma unroll
        for (int o = 16; o; o >>= 1)
            sm_merge(mm, ss, __shfl_xor_sync(0xffffffffu, mm, o), __shfl_xor_sync(0xffffffffu, ss, o));
        if (lane == 0) { shm[0] = mm; shs[0] = ss; }
    }
    __syncthreads();
    m = shm[0]; s = shs[0];
    __syncthreads();
}

__global__ void softmax_kernel(float* __restrict__ data, int N) {
    float* row = data + (size_t)blockIdx.x * N;
    float m = -1e30f, s = 0.f;
    for (int i = threadIdx.x; i < N; i += blockDim.x) {
        float v = row[i];
        float mo = m;
        m = fmaxf(m, v);
        s = s * __expf(mo - m) + __expf(v - m);
    }
    block_softmax_stats(m, s);
    const float inv = 1.f / s;
    for (int i = threadIdx.x; i < N; i += blockDim.x)
        row[i] = __expf(row[i] - m) * inv;
}

__global__ void softmax_h_kernel(const float* __restrict__ in, __half* __restrict__ o, int N)
{
    const float* row = in + (size_t)blockIdx.x * N;
    float m = -1e30f, s = 0.f;
    for (int i = threadIdx.x; i < N; i += blockDim.x) {
        float v = row[i];
        float mo = m;
        m = fmaxf(m, v);
        s = s * __expf(mo - m) + __expf(v - m);
    }
    block_softmax_stats(m, s);
    const float inv = 1.f / s;
    const size_t base = (size_t)blockIdx.x * N;
    for (int i = threadIdx.x; i < N; i += blockDim.x)
        o[base + i] = __float2half(__expf(row[i] - m) * inv);
}

// ====== fused (silu?)+residual+LayerNorm, fp32 out + fp16 out ======
template<bool SILU, bool AFFINE>
__global__ void __launch_bounds__(128) addln_kernel(
    const float* __restrict__ a, const float* __restrict__ res,
    const float* __restrict__ g, const float* __restrict__ bta,
    float* __restrict__ out, __half* __restrict__ oh)
{
    const int row = blockIdx.x;
    const int tid = threadIdx.x;
    float4 av = ((const float4*)(a   + (size_t)row * Dm))[tid];
    float4 rv = ((const float4*)(res + (size_t)row * Dm))[tid];
    float v[4] = {av.x, av.y, av.z, av.w};
    float r[4] = {rv.x, rv.y, rv.z, rv.w};

    float s = 0.f, s2 = 0.f;
    #pragma unroll
    for (int i = 0; i < 4; i++) {
        float t = SILU ? (v[i] / (1.f + __expf(-v[i]))) : v[i];
        t += r[i];
        v[i] = t;
        s += t; s2 += t * t;
    }
    __shared__ float ss[4], ss2[4];
    #pragma unroll
    for (int o = 16; o; o >>= 1) {
        s  += __shfl_xor_sync(0xffffffffu, s,  o);
        s2 += __shfl_xor_sync(0xffffffffu, s2, o);
    }
    const int w = tid >> 5, lane = tid & 31;
    if (lane == 0) { ss[w] = s; ss2[w] = s2; }
    __syncthreads();
    s  = ss[0]  + ss[1]  + ss[2]  + ss[3];
    s2 = ss2[0] + ss2[1] + ss2[2] + ss2[3];

    const float mean = s * (1.f / Dm);
    const float var  = s2 * (1.f / Dm) - mean * mean;
    const float inv  = rsqrtf(var + 1e-5f);

    float ov[4];
    #pragma unroll
    for (int i = 0; i < 4; i++) {
        float yv = (v[i] - mean) * inv;
        if (AFFINE) {
            const int c = tid * 4 + i;
            yv = yv * g[c] + bta[c];
        }
        ov[i] = yv;
    }
    float4 o4 = {ov[0], ov[1], ov[2], ov[3]};
    ((float4*)(out + (size_t)row * Dm))[tid] = o4;
    __half2 h0 = __halves2half2(__float2half(ov[0]), __float2half(ov[1]));
    __half2 h1 = __halves2half2(__float2half(ov[2]), __float2half(ov[3]));
    ((uint2*)(oh + (size_t)row * Dm))[tid] = make_uint2(*(uint32_t*)&h0, *(uint32_t*)&h1);
}

// ================= host-side orchestration =================
struct Ptrs {
    float *gx, *gout, *gh, *gh2, *gt, *ga, *gs;
    __half *x1, *o1, *h1, *h21, *q1, *p1, *k1, *v1, *vt1, *w1;
};

static void G(const __half* A, const __half* B,
              const float* bias, float* C, __half* Ch, int outm,
              int M, int N, int K, float alpha, int batch,
              long sA, long sB, long sC)
{
    dim3 grid(N / 128, M / 128, batch), block(256);
    if (outm == 1)  gemm1<1, false><<<grid, block, GEMM_SMEM>>>(A, B, bias, C, Ch, M, N, K, alpha, sA, sB, sC);
    else if (bias)  gemm1<0, true ><<<grid, block, GEMM_SMEM>>>(A, B, bias, C, Ch, M, N, K, alpha, sA, sB, sC);
    else            gemm1<0, false><<<grid, block, GEMM_SMEM>>>(A, B, bias, C, Ch, M, N, K, alpha, sA, sB, sC);
}

static void tconv(const float* in, __half* o, int R, int C) {
    dim3 grid(C / 32, R / 32), block(32, 8);
    tconvh<<<grid, block>>>(in, o, R, C);
}

// attention: out = LN( softmax((q@Wq)(ctx@Wk)^T/8) @ (ctx@Wv) + resid )
static void run_attn(const Ptrs& P,
                     const __half* q_in, const __half* c_in,
                     const float* wq, const float* wk, const float* wv,
                     const float* resid, float* outp, __half* out_h)
{
    tconv(wq, P.w1, Dm, Dm);
    G(q_in, P.w1, nullptr, nullptr, P.q1, 1, ROWS, Dm, Dm, 1.f, 1, 0, 0, 0);
    tconv(wk, P.w1, Dm, Dm);
    G(c_in, P.w1, nullptr, nullptr, P.k1, 1, ROWS, Dm, Dm, 1.f, 1, 0, 0, 0);
    tconv(wv, P.w1, Dm, Dm);
    G(c_in, P.w1, nullptr, nullptr, P.v1, 1, ROWS, Dm, Dm, 1.f, 1, 0, 0, 0);

    // scores[b] = Q[b] @ K[b]^T / 8
    G(P.q1, P.k1, nullptr, P.gs, nullptr, 0, Sq, Sq, Dm, INV_SCALE, Bsz,
      (long)Sq * Dm, (long)Sq * Dm, (long)Sq * Sq);
    softmax_h_kernel<<<ROWS, 256>>>(P.gs, P.p1, Sq);
    // V^T per batch
    {
        dim3 grid(Dm / 32, Sq / 32, Bsz), block(32, 8);
        th16<<<grid, block>>>(P.v1, P.vt1, Sq, Dm, (long)Sq * Dm);
    }
    // attn[b] = P[b] @ V[b]
    G(P.p1, P.vt1, nullptr, P.ga, nullptr, 0, Sq, Dm, Sq, 1.f, Bsz,
      (long)Sq * Sq, (long)Sq * Dm, (long)Sq * Dm);
    addln_kernel<false, false><<<ROWS, 128>>>(P.ga, resid, nullptr, nullptr, outp, out_h);
}

extern "C" void kernel_launch(void* const* d_in, const int* in_sizes, int n_in,
                              void* d_out, int out_size)
{
    const float* x       = (const float*)d_in[0];
    const float* y       = (const float*)d_in[1];
    const float* enc_wq  = (const float*)d_in[2];
    const float* enc_wk  = (const float*)d_in[3];
    const float* enc_wv  = (const float*)d_in[4];
    const float* enc_fw  = (const float*)d_in[5];
    const float* enc_fb  = (const float*)d_in[6];
    const float* enc_g   = (const float*)d_in[7];
    const float* enc_b   = (const float*)d_in[8];
    const float* dec_swq = (const float*)d_in[9];
    const float* dec_swk = (const float*)d_in[10];
    const float* dec_swv = (const float*)d_in[11];
    const float* dec_cwq = (const float*)d_in[12];
    const float* dec_cwk = (const float*)d_in[13];
    const float* dec_cwv = (const float*)d_in[14];
    const float* dec_fw  = (const float*)d_in[15];
    const float* dec_fb  = (const float*)d_in[16];
    const float* dec_g   = (const float*)d_in[17];
    const float* dec_b   = (const float*)d_in[18];
    const float* fc_w    = (const float*)d_in[19];

    cudaFuncSetAttribute(gemm1<0, false>, cudaFuncAttributeMaxDynamicSharedMemorySize, GEMM_SMEM);
    cudaFuncSetAttribute(gemm1<0, true >, cudaFuncAttributeMaxDynamicSharedMemorySize, GEMM_SMEM);
    cudaFuncSetAttribute(gemm1<1, false>, cudaFuncAttributeMaxDynamicSharedMemorySize, GEMM_SMEM);

    Ptrs P;
    cudaGetSymbolAddress((void**)&P.gx,   g_x);
    cudaGetSymbolAddress((void**)&P.gout, g_out);
    cudaGetSymbolAddress((void**)&P.gh,   g_h);
    cudaGetSymbolAddress((void**)&P.gh2,  g_h2);
    cudaGetSymbolAddress((void**)&P.gt,   g_t);
    cudaGetSymbolAddress((void**)&P.ga,   g_a);
    cudaGetSymbolAddress((void**)&P.gs,   g_s);
    cudaGetSymbolAddress((void**)&P.x1,  sx);
    cudaGetSymbolAddress((void**)&P.o1,  so);
    cudaGetSymbolAddress((void**)&P.h1,  sh);
    cudaGetSymbolAddress((void**)&P.h21, sh2);
    cudaGetSymbolAddress((void**)&P.q1,  sq);
    cudaGetSymbolAddress((void**)&P.p1,  sp);
    cudaGetSymbolAddress((void**)&P.k1,  sk);
    cudaGetSymbolAddress((void**)&P.v1,  sv);
    cudaGetSymbolAddress((void**)&P.vt1, svt);
    cudaGetSymbolAddress((void**)&P.w1,  sw);

    cudaMemcpyAsync(P.gx,   x, (size_t)BD * sizeof(float), cudaMemcpyDeviceToDevice);
    cudaMemcpyAsync(P.gout, y, (size_t)BD * sizeof(float), cudaMemcpyDeviceToDevice);
    convh<<<(BD / 4 + 255) / 256, 256>>>(x, P.x1, BD);
    convh<<<(BD / 4 + 255) / 256, 256>>>(y, P.o1, BD);

    const long DD = (long)Dm * Dm;

    // -------- encoder stacks --------
    for (int i = 0; i < Ll; i++) {
        run_attn(P, P.x1, P.x1,
                 enc_wq + i * DD, enc_wk + i * DD, enc_wv + i * DD,
                 P.gx, P.gh, P.h1);
        tconv(enc_fw + i * DD, P.w1, Dm, Dm);
        G(P.h1, P.w1, enc_fb + i * Dm, P.gt, nullptr, 0, ROWS, Dm, Dm, 1.f, 1, 0, 0, 0);
        addln_kernel<true, true><<<ROWS, 128>>>(P.gt, P.gh, enc_g + i * Dm, enc_b + i * Dm, P.gx, P.x1);
    }

    // -------- decoder stacks --------
    for (int i = 0; i < Ll; i++) {
        run_attn(P, P.x1, P.x1,
                 dec_swq + i * DD, dec_swk + i * DD, dec_swv + i * DD,
                 P.gx, P.gh, P.h1);
        run_attn(P, P.h1, P.o1,
                 dec_cwq + i * DD, dec_cwk + i * DD, dec_cwv + i * DD,
                 P.gh, P.gh2, P.h21);
        tconv(dec_fw + i * DD, P.w1, Dm, Dm);
        G(P.h21, P.w1, dec_fb + i * Dm, P.gt, nullptr, 0, ROWS, Dm, Dm, 1.f, 1, 0, 0, 0);
        addln_kernel<true, true><<<ROWS, 128>>>(P.gt, P.gh2, dec_g + i * Dm, dec_b + i * Dm, P.gout, P.o1);
    }

    // -------- vocab head + softmax --------
    tconv(fc_w, P.w1, Dm, Vv);
    float* logits = (float*)d_out;
    G(P.o1, P.w1, nullptr, logits, nullptr, 0, ROWS, Vv, Dm, 1.f, 1, 0, 0, 0);
    softmax_kernel<<<ROWS, 512>>>(logits, Vv);
}